// round 15
// baseline (speedup 1.0000x reference)
#include <cuda_runtime.h>
#include <cuda_fp16.h>

// Problem constants
#define BATCH   256          // B_
#define NTOK    256          // N tokens per window
#define DIM     192
#define HEADS   6
#define HD      32           // head dim
#define NW      64           // number of windows (mask slices)
#define ROWS    (BATCH*NTOK) // 65536 GEMM rows
#define SCALE   0.17677669529663687f   // 32^-0.5

typedef unsigned int uint;

// ---------------------------------------------------------------------------
// fp16 mma helpers (m16n8k16; gr=lane>>2, tg=lane&3)
// ---------------------------------------------------------------------------
__device__ __forceinline__ uint pkh2(float lo, float hi) {
    __half2 h = __floats2half2_rn(lo, hi);
    return *(uint*)&h;
}
__device__ __forceinline__ float2 h22f2(uint u) {
    return __half22float2(*(__half2*)&u);
}
__device__ __forceinline__ void mma16(float4& c, uint4 a, uint2 b) {
    asm("mma.sync.aligned.m16n8k16.row.col.f32.f16.f16.f32 "
        "{%0,%1,%2,%3},{%4,%5,%6,%7},{%8,%9},{%0,%1,%2,%3};"
        : "+f"(c.x), "+f"(c.y), "+f"(c.z), "+f"(c.w)
        : "r"(a.x), "r"(a.y), "r"(a.z), "r"(a.w), "r"(b.x), "r"(b.y));
}

// ---------------------------------------------------------------------------
// Scratch. q/k/v/att as packed f16 pairs; bias16/mask16 f16 tables.
// ---------------------------------------------------------------------------
__device__ uint  g_q[BATCH*HEADS*NTOK*16];
__device__ uint  g_k[BATCH*HEADS*NTOK*16];
__device__ uint  g_v[BATCH*HEADS*NTOK*16];
__device__ uint  g_att[ROWS*96];
__device__ uint  g_bias16[HEADS*NTOK*128];   // [h][n][m2] f16 pairs, 768KB
__device__ uint  g_mask16[NW*NTOK*128];      // [w][n][m2] f16 pairs, 8MB

// ---------------------------------------------------------------------------
// Prep: bias16 gather (cheap, 2 gathers/thread) + mask16 streaming convert
// ---------------------------------------------------------------------------
__global__ void bias16_kernel(const float* __restrict__ table,
                              const int* __restrict__ rel) {
    int idx = blockIdx.x * 256 + threadIdx.x;   // h*32768 + n*128 + m2
    int m2 = idx & 127;
    int n  = (idx >> 7) & 255;
    int h  = idx >> 15;
    int r0 = rel[n * 256 + 2 * m2];
    int r1 = rel[n * 256 + 2 * m2 + 1];
    g_bias16[idx] = pkh2(table[r0 * HEADS + h], table[r1 * HEADS + h]);
}
__global__ void mask16_kernel(const float* __restrict__ mask) {
    int idx = blockIdx.x * 256 + threadIdx.x;   // w*32768 + n*128 + m2
    float2 mk = *(const float2*)&mask[(size_t)idx * 2];
    g_mask16[idx] = pkh2(mk.x, mk.y);
}

// ---------------------------------------------------------------------------
// fp16 GEMM (unchanged round-13): CTA 128(M) x 96(N) x K192, grid (2,512),
// 2 CTAs/SM; chunk-major smem, 8 warps 4(M)x2(N).
// ---------------------------------------------------------------------------
#define AS_WORDS (6 * 128 * 16)   // 12288
#define BS_WORDS (6 * 96 * 16)    //  9216
#define GEMM_SMEM ((AS_WORDS + BS_WORDS) * 4)   // 86016 B

__device__ __forceinline__ uint4 ldA16(const uint* As, int mtb, int kb2,
                                       int kc, int gr, int tg) {
    int r0 = mtb + gr;
    int s  = (r0 & 7) << 1;
    const uint* base = As + (kb2 * 128 + r0) * 16;
    int c0 = (kc * 8 + tg) ^ s;
    int c1 = (kc * 8 + tg + 4) ^ s;
    uint4 a;
    a.x = base[c0];
    a.y = base[128 + c0];
    a.z = base[c1];
    a.w = base[128 + c1];
    return a;
}
__device__ __forceinline__ uint2 ldB16(const uint* Bs, int ntb, int kb2,
                                       int kc, int gr, int tg) {
    int n0 = ntb + gr;
    int s  = (n0 & 7) << 1;
    const uint* base = Bs + (kb2 * 96 + n0) * 16;
    uint2 b;
    b.x = base[(kc * 8 + tg) ^ s];
    b.y = base[(kc * 8 + tg + 4) ^ s];
    return b;
}
__device__ __forceinline__ void stageB96(uint* Bs, const float* __restrict__ W,
                                         int ldw, int cbW, int lane, int wid) {
#pragma unroll
    for (int j = 0; j < 36; j++) {
        int n  = (j % 3) * 32 + lane;
        int kg = wid + 8 * (j / 3);
        float w0 = W[(size_t)(2 * kg) * ldw + cbW + n];
        float w1 = W[(size_t)(2 * kg + 1) * ldw + cbW + n];
        int kb2 = kg >> 4;
        int col = (kg & 15) ^ ((n & 7) << 1);
        Bs[(kb2 * 96 + n) * 16 + col] = pkh2(w0, w1);
    }
}

#define GEMM_COMPUTE96()                                                       \
    _Pragma("unroll")                                                          \
    for (int kb2 = 0; kb2 < 6; kb2++) {                                        \
        _Pragma("unroll")                                                      \
        for (int kc = 0; kc < 2; kc++) {                                       \
            uint4 a[2];                                                        \
            a[0] = ldA16(As, wm * 32, kb2, kc, gr, tg);                        \
            a[1] = ldA16(As, wm * 32 + 16, kb2, kc, gr, tg);                   \
            _Pragma("unroll")                                                  \
            for (int nt = 0; nt < 6; nt++) {                                   \
                uint2 b = ldB16(Bs, wn * 48 + nt * 8, kb2, kc, gr, tg);        \
                mma16(acc[0][nt], a[0], b);                                    \
                mma16(acc[1][nt], a[1], b);                                    \
            }                                                                  \
        }                                                                      \
    }

__global__ __launch_bounds__(256, 2) void qkv_gemm_kernel(
    const float* __restrict__ X, const float* __restrict__ W,
    const float* __restrict__ bias) {
    extern __shared__ uint smg[];
    uint* As = smg;
    uint* Bs = smg + AS_WORDS;
    __shared__ float sBias[576];

    int t    = threadIdx.x;
    int lane = t & 31;
    int wid  = t >> 5;
    int wm   = wid >> 1;
    int wn   = wid & 1;
    int gr   = lane >> 2, tg = lane & 3;
    int nb   = blockIdx.x;
    int rb   = blockIdx.y * 128;

    for (int i = t; i < 576; i += 256) sBias[i] = bias[i];

#pragma unroll
    for (int ii = 0; ii < 24; ii++) {
        int fid = t + ii * 256;
        int row = fid / 48;
        int c4  = (fid - row * 48) * 4;
        float4 v = *(const float4*)&X[(size_t)(rb + row) * DIM + c4];
        int c2  = c4 >> 1;
        int kb2 = c2 >> 4;
        int col = (c2 & 15) ^ ((row & 7) << 1);
        uint2 u;
        u.x = pkh2(v.x, v.y);
        u.y = pkh2(v.z, v.w);
        *(uint2*)&As[(kb2 * 128 + row) * 16 + col] = u;
    }

    for (int mat = 0; mat < 3; mat++) {
        __syncthreads();
        stageB96(Bs, W, 576, mat * 192 + nb * 96, lane, wid);
        __syncthreads();

        float4 acc[2][6];
#pragma unroll
        for (int i = 0; i < 2; i++)
#pragma unroll
            for (int j = 0; j < 6; j++) acc[i][j] = make_float4(0.f, 0.f, 0.f, 0.f);

        GEMM_COMPUTE96()

        uint* dst = (mat == 0) ? g_q : (mat == 1) ? g_k : g_v;
        float sc = (mat == 0) ? SCALE : 1.f;
#pragma unroll
        for (int mt = 0; mt < 2; mt++) {
#pragma unroll
            for (int nt = 0; nt < 6; nt++) {
                float4 c = acc[mt][nt];
                int cl = nb * 96 + wn * 48 + nt * 8 + 2 * tg;
                float b0 = sBias[mat * 192 + cl], b1 = sBias[mat * 192 + cl + 1];
                int h = cl >> 5, d2 = (cl & 31) >> 1;
                int r0 = rb + wm * 32 + mt * 16 + gr;
                uint u0 = pkh2((c.x + b0) * sc, (c.y + b1) * sc);
                uint u1 = pkh2((c.z + b0) * sc, (c.w + b1) * sc);
                dst[(((r0 >> 8) * HEADS + h) * 256 + (r0 & 255)) * 16 + d2] = u0;
                int r1 = r0 + 8;
                dst[(((r1 >> 8) * HEADS + h) * 256 + (r1 & 255)) * 16 + d2] = u1;
            }
        }
    }
}

__global__ __launch_bounds__(256, 2) void proj_gemm_kernel(
    const float* __restrict__ W, const float* __restrict__ bias,
    float* __restrict__ out) {
    extern __shared__ uint smg[];
    uint* As = smg;
    uint* Bs = smg + AS_WORDS;
    __shared__ float sBias[192];

    int t    = threadIdx.x;
    int lane = t & 31;
    int wid  = t >> 5;
    int wm   = wid >> 1;
    int wn   = wid & 1;
    int gr   = lane >> 2, tg = lane & 3;
    int nb   = blockIdx.x;
    int rb   = blockIdx.y * 128;

    if (t < 192) sBias[t] = bias[t];

#pragma unroll
    for (int ii = 0; ii < 24; ii++) {
        int fid = t + ii * 256;
        int row = fid / 48;
        int c2  = (fid - row * 48) * 2;
        uint2 v = *(const uint2*)&g_att[(size_t)(rb + row) * 96 + c2];
        int kb2 = c2 >> 4;
        int col = (c2 & 15) ^ ((row & 7) << 1);
        *(uint2*)&As[(kb2 * 128 + row) * 16 + col] = v;
    }
    stageB96(Bs, W, DIM, nb * 96, lane, wid);
    __syncthreads();

    float4 acc[2][6];
#pragma unroll
    for (int i = 0; i < 2; i++)
#pragma unroll
        for (int j = 0; j < 6; j++) acc[i][j] = make_float4(0.f, 0.f, 0.f, 0.f);

    GEMM_COMPUTE96()

#pragma unroll
    for (int mt = 0; mt < 2; mt++) {
#pragma unroll
        for (int nt = 0; nt < 6; nt++) {
            float4 c = acc[mt][nt];
            int cl = nb * 96 + wn * 48 + nt * 8 + 2 * tg;
            float b0 = sBias[cl], b1 = sBias[cl + 1];
            int r0 = rb + wm * 32 + mt * 16 + gr;
            *(float2*)&out[(size_t)r0 * DIM + cl] =
                make_float2(c.x + b0, c.y + b1);
            *(float2*)&out[(size_t)(r0 + 8) * DIM + cl] =
                make_float2(c.z + b0, c.w + b1);
        }
    }
}

// ---------------------------------------------------------------------------
// fp16 tensor-core attention (R13 structure). One CTA per (b,h); bm staged
// from the two f16 tables (256KB/CTA vs 512KB), added in f32, WB unchanged.
// ---------------------------------------------------------------------------
__global__ __launch_bounds__(256, 2) void attn_f16_kernel() {
    extern __shared__ uint sm[];
    uint* Ks  = sm;                 // 4096 u32
    uint* Vs  = sm + 4096;          // 4096 u32
    uint* Qs  = sm + 8192;          // 4096 u32 (transient, inside WB)
    float* WB = (float*)(sm + 8192);// 8192 f32 (8 x 1024 per-warp)

    int h = blockIdx.x;
    int b = blockIdx.y;
    int w = b & (NW - 1);
    int t = threadIdx.x;
    int lane = t & 31;
    int wid = t >> 5;
    int gr = lane >> 2, tg = lane & 3;

    const uint* kg = g_k + (size_t)(b * HEADS + h) * (256 * 16);
    const uint* qg = g_q + (size_t)(b * HEADS + h) * (256 * 16);
    const uint* vg = g_v + (size_t)(b * HEADS + h) * (256 * 16);

#pragma unroll
    for (int i = 0; i < 8; i++) {
        int fid = t + i * 256;
        int key = fid >> 3;
        int p   = (fid & 7) * 2;
        int col = p ^ ((key & 7) << 1);
        *(uint2*)&Ks[key * 16 + col] = *(const uint2*)&kg[key * 16 + p];
        *(uint2*)&Qs[key * 16 + col] = *(const uint2*)&qg[key * 16 + p];
    }
#pragma unroll
    for (int i = 0; i < 4; i++) {
        int fid = t + i * 256;
        int k2  = fid >> 3;
        int dg  = (fid & 7) * 4;
        uint2 r0 = *(const uint2*)&vg[(2 * k2) * 16 + (dg >> 1)];
        uint2 r1 = *(const uint2*)&vg[(2 * k2 + 1) * 16 + (dg >> 1)];
        uint4 o;
        o.x = __byte_perm(r0.x, r1.x, 0x5410);
        o.y = __byte_perm(r0.x, r1.x, 0x7632);
        o.z = __byte_perm(r0.y, r1.y, 0x5410);
        o.w = __byte_perm(r0.y, r1.y, 0x7632);
        *(uint4*)&Vs[k2 * 32 + (dg ^ ((k2 & 3) << 3))] = o;
    }
    __syncthreads();

    int qb = wid * 32;
    uint4 qa[2][2];
#pragma unroll
    for (int mi = 0; mi < 2; mi++) {
#pragma unroll
        for (int kc = 0; kc < 2; kc++) {
            int r0 = qb + mi * 16 + gr;
            int s  = (r0 & 7) << 1;
            qa[mi][kc].x = Qs[r0 * 16 + ((kc * 8 + tg) ^ s)];
            qa[mi][kc].y = Qs[(r0 + 8) * 16 + ((kc * 8 + tg) ^ s)];
            qa[mi][kc].z = Qs[r0 * 16 + ((kc * 8 + tg + 4) ^ s)];
            qa[mi][kc].w = Qs[(r0 + 8) * 16 + ((kc * 8 + tg + 4) ^ s)];
        }
    }
    __syncthreads();   // Qs region now free -> per-warp WB

    float* Pf = WB + wid * 1024;
    float4 O[2][4];
#pragma unroll
    for (int mi = 0; mi < 2; mi++)
#pragma unroll
        for (int nt = 0; nt < 4; nt++) O[mi][nt] = make_float4(0.f, 0.f, 0.f, 0.f);
    float lsum[2][2] = {{0.f, 0.f}, {0.f, 0.f}};

    const uint* Bb16 = g_bias16 + (((size_t)h) << 15) + ((size_t)qb << 7);
    const uint* Mb16 = g_mask16 + (((size_t)w) << 15) + ((size_t)qb << 7);
    int ern = lane >> 2;            // staging row group 0..7
    int erc = (lane & 3) * 4;       // u32 col 0,4,8,12
    int C2  = 2 * tg;

    for (int ch = 0; ch < 8; ch++) {
        int cb2 = ch * 16;    // u32 col base in table row
        // ---- stage bias16+mask16 32x32 -> WB f32 (coalesced LDG.128) ----
        {
#pragma unroll
            for (int i = 0; i < 4; i++) {
                int n = i * 8 + ern;
                uint4 bv = *(const uint4*)(Bb16 + ((size_t)n << 7) + cb2 + erc);
                uint4 mv = *(const uint4*)(Mb16 + ((size_t)n << 7) + cb2 + erc);
                float2 b0 = h22f2(bv.x), m0 = h22f2(mv.x);
                float2 b1 = h22f2(bv.y), m1 = h22f2(mv.y);
                float2 b2 = h22f2(bv.z), m2 = h22f2(mv.z);
                float2 b3 = h22f2(bv.w), m3 = h22f2(mv.w);
                int m = erc * 2;   // 0,8,16,24
                *(float4*)(Pf + n * 32 + (m ^ ((n & 3) << 3))) =
                    make_float4(b0.x + m0.x, b0.y + m0.y, b1.x + m1.x, b1.y + m1.y);
                *(float4*)(Pf + n * 32 + ((m + 4) ^ ((n & 3) << 3))) =
                    make_float4(b2.x + m2.x, b2.y + m2.y, b3.x + m3.x, b3.y + m3.y);
            }
        }
        __syncwarp();

        // ---- S = Q * K^T (32 keys) ----
        float4 S[2][4];
#pragma unroll
        for (int mi = 0; mi < 2; mi++)
#pragma unroll
            for (int nt = 0; nt < 4; nt++) S[mi][nt] = make_float4(0.f, 0.f, 0.f, 0.f);
#pragma unroll
        for (int kc = 0; kc < 2; kc++) {
#pragma unroll
            for (int nt = 0; nt < 4; nt++) {
                int key = ch * 32 + nt * 8 + gr;
                int s2  = (key & 7) << 1;
                uint2 bk;
                bk.x = Ks[key * 16 + ((kc * 8 + tg) ^ s2)];
                bk.y = Ks[key * 16 + ((kc * 8 + tg + 4) ^ s2)];
                mma16(S[0][nt], qa[0][kc], bk);
                mma16(S[1][nt], qa[1][kc], bk);
            }
        }

        // ---- softmax numerators; pack P straight into fp16 A-frags ----
        uint4 pa[2][2];
#pragma unroll
        for (int mi = 0; mi < 2; mi++) {
#pragma unroll
            for (int nt = 0; nt < 4; nt++) {
                int n0 = mi * 16 + gr;
                int m  = nt * 8 + C2;
                float2 bm0 = *(const float2*)(Pf + n0 * 32 + (m ^ ((n0 & 3) << 3)));
                int n1 = n0 + 8;
                float2 bm1 = *(const float2*)(Pf + n1 * 32 + (m ^ ((n1 & 3) << 3)));
                float4 s = S[mi][nt];
                float p00 = __expf(s.x + bm0.x);
                float p01 = __expf(s.y + bm0.y);
                float p10 = __expf(s.z + bm1.x);
                float p11 = __expf(s.w + bm1.y);
                lsum[mi][0] += p00 + p01;
                lsum[mi][1] += p10 + p11;
                uint lo = pkh2(p00, p01);
                uint hi = pkh2(p10, p11);
                int jj = nt >> 1;
                if ((nt & 1) == 0) { pa[mi][jj].x = lo; pa[mi][jj].y = hi; }
                else               { pa[mi][jj].z = lo; pa[mi][jj].w = hi; }
            }
        }
        __syncwarp();

        // ---- O += P * V ----
#pragma unroll
        for (int jj = 0; jj < 2; jj++) {
            int k2b = ch * 16 + jj * 8;
            int rA = k2b + tg, rB = k2b + tg + 4;
#pragma unroll
            for (int nt = 0; nt < 4; nt++) {
                int d0 = nt * 8 + gr;
                uint2 vb;
                vb.x = Vs[rA * 32 + (d0 ^ ((rA & 3) << 3))];
                vb.y = Vs[rB * 32 + (d0 ^ ((rB & 3) << 3))];
                mma16(O[0][nt], pa[0][jj], vb);
                mma16(O[1][nt], pa[1][jj], vb);
            }
        }
    }

    float inv[2][2];
#pragma unroll
    for (int mi = 0; mi < 2; mi++)
#pragma unroll
        for (int r2 = 0; r2 < 2; r2++) {
            float lv = lsum[mi][r2];
            lv += __shfl_xor_sync(0xffffffff, lv, 1);
            lv += __shfl_xor_sync(0xffffffff, lv, 2);
            inv[mi][r2] = 1.f / lv;
        }
#pragma unroll
    for (int mi = 0; mi < 2; mi++) {
#pragma unroll
        for (int nt = 0; nt < 4; nt++) {
            float4 o = O[mi][nt];
            int r0 = b * 256 + qb + mi * 16 + gr;
            int col = h * 16 + nt * 4 + tg;
            g_att[(size_t)r0 * 96 + col] =
                pkh2(o.x * inv[mi][0], o.y * inv[mi][0]);
            g_att[(size_t)(r0 + 8) * 96 + col] =
                pkh2(o.z * inv[mi][1], o.w * inv[mi][1]);
        }
    }
}

// ---------------------------------------------------------------------------
// Launch
// ---------------------------------------------------------------------------
extern "C" void kernel_launch(void* const* d_in, const int* in_sizes, int n_in,
                              void* d_out, int out_size) {
    const float* x        = (const float*)d_in[0];
    const float* mask     = (const float*)d_in[1];
    const float* qkv_w    = (const float*)d_in[2];
    const float* qkv_b    = (const float*)d_in[3];
    const float* proj_w   = (const float*)d_in[4];
    const float* proj_b   = (const float*)d_in[5];
    const float* table    = (const float*)d_in[6];
    const int*   rel      = (const int*)d_in[7];
    float* out = (float*)d_out;

    cudaFuncSetAttribute(attn_f16_kernel,
                         cudaFuncAttributeMaxDynamicSharedMemorySize, 65536);
    cudaFuncSetAttribute(qkv_gemm_kernel,
                         cudaFuncAttributeMaxDynamicSharedMemorySize, GEMM_SMEM);
    cudaFuncSetAttribute(proj_gemm_kernel,
                         cudaFuncAttributeMaxDynamicSharedMemorySize, GEMM_SMEM);

    bias16_kernel<<<HEADS * NTOK * 128 / 256, 256>>>(table, rel);
    mask16_kernel<<<NW * NTOK * 128 / 256, 256>>>(mask);
    qkv_gemm_kernel<<<dim3(2, ROWS / 128), 256, GEMM_SMEM>>>(x, qkv_w, qkv_b);
    attn_f16_kernel<<<dim3(HEADS, BATCH), 256, 65536>>>();
    proj_gemm_kernel<<<dim3(2, ROWS / 128), 256, GEMM_SMEM>>>(proj_w, proj_b, out);
}

// round 16
// speedup vs baseline: 1.0612x; 1.0612x over previous
#include <cuda_runtime.h>
#include <cuda_fp16.h>

// Problem constants
#define BATCH   256          // B_
#define NTOK    256          // N tokens per window
#define DIM     192
#define HEADS   6
#define HD      32           // head dim
#define NW      64           // number of windows (mask slices)
#define ROWS    (BATCH*NTOK) // 65536 GEMM rows
#define SCALE   0.17677669529663687f   // 32^-0.5

typedef unsigned int uint;

// ---------------------------------------------------------------------------
// fp16 mma helpers (m16n8k16; gr=lane>>2, tg=lane&3)
// ---------------------------------------------------------------------------
__device__ __forceinline__ uint pkh2(float lo, float hi) {
    __half2 h = __floats2half2_rn(lo, hi);
    return *(uint*)&h;
}
__device__ __forceinline__ float2 h22f2(uint u) {
    return __half22float2(*(__half2*)&u);
}
__device__ __forceinline__ void mma16(float4& c, uint4 a, uint2 b) {
    asm("mma.sync.aligned.m16n8k16.row.col.f32.f16.f16.f32 "
        "{%0,%1,%2,%3},{%4,%5,%6,%7},{%8,%9},{%0,%1,%2,%3};"
        : "+f"(c.x), "+f"(c.y), "+f"(c.z), "+f"(c.w)
        : "r"(a.x), "r"(a.y), "r"(a.z), "r"(a.w), "r"(b.x), "r"(b.y));
}

// ---------------------------------------------------------------------------
// Scratch. q/k/v/att packed f16 pairs. bias/mask pre-permuted into FRAGMENT
// ORDER: G[outer][ch(8)][wid(8)][lane(32)][j(16)] u32 (f16 pair), where
// j = mi*8 + r2*4 + nt gives the value at
//   n = wid*32 + mi*16 + r2*8 + (lane>>2),  m2 = ch*16 + nt*4 + (lane&3).
// Attn reads these with coalesced LDG.128 directly into fragment registers.
// ---------------------------------------------------------------------------
__device__ uint  g_q[BATCH*HEADS*NTOK*16];
__device__ uint  g_k[BATCH*HEADS*NTOK*16];
__device__ uint  g_v[BATCH*HEADS*NTOK*16];
__device__ uint  g_att[ROWS*96];
__device__ uint  g_bias16f[HEADS*8*8*512];   // 786KB
__device__ uint  g_mask16f[NW*8*8*512];      // 8MB

// ---------------------------------------------------------------------------
// Prep: bias gather -> frag order (grid (8 nb, 6 h))
// ---------------------------------------------------------------------------
__global__ void bias16f_kernel(const float* __restrict__ table,
                               const int* __restrict__ rel) {
    __shared__ uint tile[32 * 130];
    int nb = blockIdx.x, h = blockIdx.y, t = threadIdx.x;
#pragma unroll
    for (int i = 0; i < 16; i++) {
        int fid = t + i * 256;          // 4096 = 32 rows x 128 m2
        int r = fid >> 7, m2 = fid & 127;
        int n = nb * 32 + r;
        int r0 = rel[n * 256 + 2 * m2];
        int r1 = rel[n * 256 + 2 * m2 + 1];
        tile[r * 130 + m2] = pkh2(table[r0 * HEADS + h], table[r1 * HEADS + h]);
    }
    __syncthreads();
    for (int ch = 0; ch < 8; ch++) {
#pragma unroll
        for (int k = 0; k < 2; k++) {
            int o = t * 2 + k;          // 512 words per (h,ch,nb)
            int lane = o >> 4, j = o & 15;
            int mi = j >> 3, r2 = (j >> 2) & 1, nt = j & 3;
            int rl = mi * 16 + r2 * 8 + (lane >> 2);
            int m2 = ch * 16 + nt * 4 + (lane & 3);
            g_bias16f[((((size_t)h * 8 + ch) * 8 + nb) << 9) + o] =
                tile[rl * 130 + m2];
        }
    }
}

// Prep: mask convert -> frag order (grid (8 nb, 64 w))
__global__ void mask16f_kernel(const float* __restrict__ mask) {
    __shared__ uint tile[32 * 130];
    int nb = blockIdx.x, w = blockIdx.y, t = threadIdx.x;
#pragma unroll
    for (int i = 0; i < 8; i++) {
        int fid = t + i * 256;          // 2048 float4 = 32 rows x 64
        int r = fid >> 6, f4 = fid & 63;
        float4 v = *(const float4*)&mask[((size_t)(w * 256 + nb * 32 + r)) * 256 + f4 * 4];
        tile[r * 130 + f4 * 2]     = pkh2(v.x, v.y);
        tile[r * 130 + f4 * 2 + 1] = pkh2(v.z, v.w);
    }
    __syncthreads();
    for (int ch = 0; ch < 8; ch++) {
#pragma unroll
        for (int k = 0; k < 2; k++) {
            int o = t * 2 + k;
            int lane = o >> 4, j = o & 15;
            int mi = j >> 3, r2 = (j >> 2) & 1, nt = j & 3;
            int rl = mi * 16 + r2 * 8 + (lane >> 2);
            int m2 = ch * 16 + nt * 4 + (lane & 3);
            g_mask16f[((((size_t)w * 8 + ch) * 8 + nb) << 9) + o] =
                tile[rl * 130 + m2];
        }
    }
}

// ---------------------------------------------------------------------------
// fp16 GEMM (unchanged, best R13 config): CTA 128x96xK192, grid (2,512),
// 2 CTAs/SM; chunk-major smem, 8 warps 4(M)x2(N).
// ---------------------------------------------------------------------------
#define AS_WORDS (6 * 128 * 16)   // 12288
#define BS_WORDS (6 * 96 * 16)    //  9216
#define GEMM_SMEM ((AS_WORDS + BS_WORDS) * 4)   // 86016 B

__device__ __forceinline__ uint4 ldA16(const uint* As, int mtb, int kb2,
                                       int kc, int gr, int tg) {
    int r0 = mtb + gr;
    int s  = (r0 & 7) << 1;
    const uint* base = As + (kb2 * 128 + r0) * 16;
    int c0 = (kc * 8 + tg) ^ s;
    int c1 = (kc * 8 + tg + 4) ^ s;
    uint4 a;
    a.x = base[c0];
    a.y = base[128 + c0];
    a.z = base[c1];
    a.w = base[128 + c1];
    return a;
}
__device__ __forceinline__ uint2 ldB16(const uint* Bs, int ntb, int kb2,
                                       int kc, int gr, int tg) {
    int n0 = ntb + gr;
    int s  = (n0 & 7) << 1;
    const uint* base = Bs + (kb2 * 96 + n0) * 16;
    uint2 b;
    b.x = base[(kc * 8 + tg) ^ s];
    b.y = base[(kc * 8 + tg + 4) ^ s];
    return b;
}
__device__ __forceinline__ void stageB96(uint* Bs, const float* __restrict__ W,
                                         int ldw, int cbW, int lane, int wid) {
#pragma unroll
    for (int j = 0; j < 36; j++) {
        int n  = (j % 3) * 32 + lane;
        int kg = wid + 8 * (j / 3);
        float w0 = W[(size_t)(2 * kg) * ldw + cbW + n];
        float w1 = W[(size_t)(2 * kg + 1) * ldw + cbW + n];
        int kb2 = kg >> 4;
        int col = (kg & 15) ^ ((n & 7) << 1);
        Bs[(kb2 * 96 + n) * 16 + col] = pkh2(w0, w1);
    }
}

#define GEMM_COMPUTE96()                                                       \
    _Pragma("unroll")                                                          \
    for (int kb2 = 0; kb2 < 6; kb2++) {                                        \
        _Pragma("unroll")                                                      \
        for (int kc = 0; kc < 2; kc++) {                                       \
            uint4 a[2];                                                        \
            a[0] = ldA16(As, wm * 32, kb2, kc, gr, tg);                        \
            a[1] = ldA16(As, wm * 32 + 16, kb2, kc, gr, tg);                   \
            _Pragma("unroll")                                                  \
            for (int nt = 0; nt < 6; nt++) {                                   \
                uint2 b = ldB16(Bs, wn * 48 + nt * 8, kb2, kc, gr, tg);        \
                mma16(acc[0][nt], a[0], b);                                    \
                mma16(acc[1][nt], a[1], b);                                    \
            }                                                                  \
        }                                                                      \
    }

__global__ __launch_bounds__(256, 2) void qkv_gemm_kernel(
    const float* __restrict__ X, const float* __restrict__ W,
    const float* __restrict__ bias) {
    extern __shared__ uint smg[];
    uint* As = smg;
    uint* Bs = smg + AS_WORDS;
    __shared__ float sBias[576];

    int t    = threadIdx.x;
    int lane = t & 31;
    int wid  = t >> 5;
    int wm   = wid >> 1;
    int wn   = wid & 1;
    int gr   = lane >> 2, tg = lane & 3;
    int nb   = blockIdx.x;
    int rb   = blockIdx.y * 128;

    for (int i = t; i < 576; i += 256) sBias[i] = bias[i];

#pragma unroll
    for (int ii = 0; ii < 24; ii++) {
        int fid = t + ii * 256;
        int row = fid / 48;
        int c4  = (fid - row * 48) * 4;
        float4 v = *(const float4*)&X[(size_t)(rb + row) * DIM + c4];
        int c2  = c4 >> 1;
        int kb2 = c2 >> 4;
        int col = (c2 & 15) ^ ((row & 7) << 1);
        uint2 u;
        u.x = pkh2(v.x, v.y);
        u.y = pkh2(v.z, v.w);
        *(uint2*)&As[(kb2 * 128 + row) * 16 + col] = u;
    }

    for (int mat = 0; mat < 3; mat++) {
        __syncthreads();
        stageB96(Bs, W, 576, mat * 192 + nb * 96, lane, wid);
        __syncthreads();

        float4 acc[2][6];
#pragma unroll
        for (int i = 0; i < 2; i++)
#pragma unroll
            for (int j = 0; j < 6; j++) acc[i][j] = make_float4(0.f, 0.f, 0.f, 0.f);

        GEMM_COMPUTE96()

        uint* dst = (mat == 0) ? g_q : (mat == 1) ? g_k : g_v;
        float sc = (mat == 0) ? SCALE : 1.f;
#pragma unroll
        for (int mt = 0; mt < 2; mt++) {
#pragma unroll
            for (int nt = 0; nt < 6; nt++) {
                float4 c = acc[mt][nt];
                int cl = nb * 96 + wn * 48 + nt * 8 + 2 * tg;
                float b0 = sBias[mat * 192 + cl], b1 = sBias[mat * 192 + cl + 1];
                int h = cl >> 5, d2 = (cl & 31) >> 1;
                int r0 = rb + wm * 32 + mt * 16 + gr;
                uint u0 = pkh2((c.x + b0) * sc, (c.y + b1) * sc);
                uint u1 = pkh2((c.z + b0) * sc, (c.w + b1) * sc);
                dst[(((r0 >> 8) * HEADS + h) * 256 + (r0 & 255)) * 16 + d2] = u0;
                int r1 = r0 + 8;
                dst[(((r1 >> 8) * HEADS + h) * 256 + (r1 & 255)) * 16 + d2] = u1;
            }
        }
    }
}

__global__ __launch_bounds__(256, 2) void proj_gemm_kernel(
    const float* __restrict__ W, const float* __restrict__ bias,
    float* __restrict__ out) {
    extern __shared__ uint smg[];
    uint* As = smg;
    uint* Bs = smg + AS_WORDS;
    __shared__ float sBias[192];

    int t    = threadIdx.x;
    int lane = t & 31;
    int wid  = t >> 5;
    int wm   = wid >> 1;
    int wn   = wid & 1;
    int gr   = lane >> 2, tg = lane & 3;
    int nb   = blockIdx.x;
    int rb   = blockIdx.y * 128;

    if (t < 192) sBias[t] = bias[t];

#pragma unroll
    for (int ii = 0; ii < 24; ii++) {
        int fid = t + ii * 256;
        int row = fid / 48;
        int c2  = (fid - row * 48) * 2;
        uint2 v = *(const uint2*)&g_att[(size_t)(rb + row) * 96 + c2];
        int kb2 = c2 >> 4;
        int col = (c2 & 15) ^ ((row & 7) << 1);
        *(uint2*)&As[(kb2 * 128 + row) * 16 + col] = v;
    }
    stageB96(Bs, W, DIM, nb * 96, lane, wid);
    __syncthreads();

    float4 acc[2][6];
#pragma unroll
    for (int i = 0; i < 2; i++)
#pragma unroll
        for (int j = 0; j < 6; j++) acc[i][j] = make_float4(0.f, 0.f, 0.f, 0.f);

    GEMM_COMPUTE96()

#pragma unroll
    for (int mt = 0; mt < 2; mt++) {
#pragma unroll
        for (int nt = 0; nt < 6; nt++) {
            float4 c = acc[mt][nt];
            int cl = nb * 96 + wn * 48 + nt * 8 + 2 * tg;
            float b0 = sBias[cl], b1 = sBias[cl + 1];
            int r0 = rb + wm * 32 + mt * 16 + gr;
            *(float2*)&out[(size_t)r0 * DIM + cl] =
                make_float2(c.x + b0, c.y + b1);
            *(float2*)&out[(size_t)(r0 + 8) * DIM + cl] =
                make_float2(c.z + b0, c.w + b1);
        }
    }
}

// ---------------------------------------------------------------------------
// fp16 tensor-core attention. One CTA per (b,h); 8 warps x 32 query rows.
// bm values arrive in FRAGMENT ORDER via 8 coalesced LDG.128/warp-chunk —
// no smem staging, no WB buffer. smem = Q/K/V tiles only (48KB).
// ---------------------------------------------------------------------------
__global__ __launch_bounds__(256, 2) void attn_f16_kernel() {
    extern __shared__ uint sm[];
    uint* Ks  = sm;                 // 4096 u32
    uint* Vs  = sm + 4096;          // 4096 u32
    uint* Qs  = sm + 8192;          // 4096 u32

    int h = blockIdx.x;
    int b = blockIdx.y;
    int w = b & (NW - 1);
    int t = threadIdx.x;
    int lane = t & 31;
    int wid = t >> 5;
    int gr = lane >> 2, tg = lane & 3;

    const uint* kg = g_k + (size_t)(b * HEADS + h) * (256 * 16);
    const uint* qg = g_q + (size_t)(b * HEADS + h) * (256 * 16);
    const uint* vg = g_v + (size_t)(b * HEADS + h) * (256 * 16);

#pragma unroll
    for (int i = 0; i < 8; i++) {
        int fid = t + i * 256;
        int key = fid >> 3;
        int p   = (fid & 7) * 2;
        int col = p ^ ((key & 7) << 1);
        *(uint2*)&Ks[key * 16 + col] = *(const uint2*)&kg[key * 16 + p];
        *(uint2*)&Qs[key * 16 + col] = *(const uint2*)&qg[key * 16 + p];
    }
#pragma unroll
    for (int i = 0; i < 4; i++) {
        int fid = t + i * 256;
        int k2  = fid >> 3;
        int dg  = (fid & 7) * 4;
        uint2 r0 = *(const uint2*)&vg[(2 * k2) * 16 + (dg >> 1)];
        uint2 r1 = *(const uint2*)&vg[(2 * k2 + 1) * 16 + (dg >> 1)];
        uint4 o;
        o.x = __byte_perm(r0.x, r1.x, 0x5410);
        o.y = __byte_perm(r0.x, r1.x, 0x7632);
        o.z = __byte_perm(r0.y, r1.y, 0x5410);
        o.w = __byte_perm(r0.y, r1.y, 0x7632);
        *(uint4*)&Vs[k2 * 32 + (dg ^ ((k2 & 3) << 3))] = o;
    }
    __syncthreads();

    int qb = wid * 32;
    uint4 qa[2][2];
#pragma unroll
    for (int mi = 0; mi < 2; mi++) {
#pragma unroll
        for (int kc = 0; kc < 2; kc++) {
            int r0 = qb + mi * 16 + gr;
            int s  = (r0 & 7) << 1;
            qa[mi][kc].x = Qs[r0 * 16 + ((kc * 8 + tg) ^ s)];
            qa[mi][kc].y = Qs[(r0 + 8) * 16 + ((kc * 8 + tg) ^ s)];
            qa[mi][kc].z = Qs[r0 * 16 + ((kc * 8 + tg + 4) ^ s)];
            qa[mi][kc].w = Qs[(r0 + 8) * 16 + ((kc * 8 + tg + 4) ^ s)];
        }
    }

    float4 O[2][4];
#pragma unroll
    for (int mi = 0; mi < 2; mi++)
#pragma unroll
        for (int nt = 0; nt < 4; nt++) O[mi][nt] = make_float4(0.f, 0.f, 0.f, 0.f);
    float lsum[2][2] = {{0.f, 0.f}, {0.f, 0.f}};

    // frag-ordered table base pointers for this (h/w, wid, lane)
    const uint* Bp = g_bias16f + ((((size_t)h * 8) * 8 + wid) << 9) + lane * 16;
    const uint* Mp = g_mask16f + ((((size_t)w * 8) * 8 + wid) << 9) + lane * 16;

    for (int ch = 0; ch < 8; ch++) {
        // ---- coalesced frag-order bm loads (overlap with S-mma below) ----
        uint bf[16], mf[16];
        {
            const uint* bq = Bp + (size_t)ch * 4096;
            const uint* mq = Mp + (size_t)ch * 4096;
#pragma unroll
            for (int i = 0; i < 4; i++) {
                *(uint4*)&bf[i * 4] = *(const uint4*)(bq + i * 4);
                *(uint4*)&mf[i * 4] = *(const uint4*)(mq + i * 4);
            }
        }

        // ---- S = Q * K^T (32 keys) ----
        float4 S[2][4];
#pragma unroll
        for (int mi = 0; mi < 2; mi++)
#pragma unroll
            for (int nt = 0; nt < 4; nt++) S[mi][nt] = make_float4(0.f, 0.f, 0.f, 0.f);
#pragma unroll
        for (int kc = 0; kc < 2; kc++) {
#pragma unroll
            for (int nt = 0; nt < 4; nt++) {
                int key = ch * 32 + nt * 8 + gr;
                int s2  = (key & 7) << 1;
                uint2 bk;
                bk.x = Ks[key * 16 + ((kc * 8 + tg) ^ s2)];
                bk.y = Ks[key * 16 + ((kc * 8 + tg + 4) ^ s2)];
                mma16(S[0][nt], qa[0][kc], bk);
                mma16(S[1][nt], qa[1][kc], bk);
            }
        }

        // ---- softmax numerators; pack P straight into fp16 A-frags ----
        uint4 pa[2][2];
#pragma unroll
        for (int mi = 0; mi < 2; mi++) {
#pragma unroll
            for (int nt = 0; nt < 4; nt++) {
                float2 b0 = h22f2(bf[(mi * 2 + 0) * 4 + nt]);
                float2 m0 = h22f2(mf[(mi * 2 + 0) * 4 + nt]);
                float2 b1 = h22f2(bf[(mi * 2 + 1) * 4 + nt]);
                float2 m1 = h22f2(mf[(mi * 2 + 1) * 4 + nt]);
                float4 s = S[mi][nt];
                float p00 = __expf(s.x + b0.x + m0.x);
                float p01 = __expf(s.y + b0.y + m0.y);
                float p10 = __expf(s.z + b1.x + m1.x);
                float p11 = __expf(s.w + b1.y + m1.y);
                lsum[mi][0] += p00 + p01;
                lsum[mi][1] += p10 + p11;
                uint lo = pkh2(p00, p01);
                uint hi = pkh2(p10, p11);
                int jj = nt >> 1;
                if ((nt & 1) == 0) { pa[mi][jj].x = lo; pa[mi][jj].y = hi; }
                else               { pa[mi][jj].z = lo; pa[mi][jj].w = hi; }
            }
        }

        // ---- O += P * V ----
#pragma unroll
        for (int jj = 0; jj < 2; jj++) {
            int k2b = ch * 16 + jj * 8;
            int rA = k2b + tg, rB = k2b + tg + 4;
#pragma unroll
            for (int nt = 0; nt < 4; nt++) {
                int d0 = nt * 8 + gr;
                uint2 vb;
                vb.x = Vs[rA * 32 + (d0 ^ ((rA & 3) << 3))];
                vb.y = Vs[rB * 32 + (d0 ^ ((rB & 3) << 3))];
                mma16(O[0][nt], pa[0][jj], vb);
                mma16(O[1][nt], pa[1][jj], vb);
            }
        }
    }

    float inv[2][2];
#pragma unroll
    for (int mi = 0; mi < 2; mi++)
#pragma unroll
        for (int r2 = 0; r2 < 2; r2++) {
            float lv = lsum[mi][r2];
            lv += __shfl_xor_sync(0xffffffff, lv, 1);
            lv += __shfl_xor_sync(0xffffffff, lv, 2);
            inv[mi][r2] = 1.f / lv;
        }
#pragma unroll
    for (int mi = 0; mi < 2; mi++) {
#pragma unroll
        for (int nt = 0; nt < 4; nt++) {
            float4 o = O[mi][nt];
            int r0 = b * 256 + qb + mi * 16 + gr;
            int col = h * 16 + nt * 4 + tg;
            g_att[(size_t)r0 * 96 + col] =
                pkh2(o.x * inv[mi][0], o.y * inv[mi][0]);
            g_att[(size_t)(r0 + 8) * 96 + col] =
                pkh2(o.z * inv[mi][1], o.w * inv[mi][1]);
        }
    }
}

// ---------------------------------------------------------------------------
// Launch
// ---------------------------------------------------------------------------
extern "C" void kernel_launch(void* const* d_in, const int* in_sizes, int n_in,
                              void* d_out, int out_size) {
    const float* x        = (const float*)d_in[0];
    const float* mask     = (const float*)d_in[1];
    const float* qkv_w    = (const float*)d_in[2];
    const float* qkv_b    = (const float*)d_in[3];
    const float* proj_w   = (const float*)d_in[4];
    const float* proj_b   = (const float*)d_in[5];
    const float* table    = (const float*)d_in[6];
    const int*   rel      = (const int*)d_in[7];
    float* out = (float*)d_out;

    cudaFuncSetAttribute(attn_f16_kernel,
                         cudaFuncAttributeMaxDynamicSharedMemorySize, 49152);
    cudaFuncSetAttribute(qkv_gemm_kernel,
                         cudaFuncAttributeMaxDynamicSharedMemorySize, GEMM_SMEM);
    cudaFuncSetAttribute(proj_gemm_kernel,
                         cudaFuncAttributeMaxDynamicSharedMemorySize, GEMM_SMEM);

    bias16f_kernel<<<dim3(8, HEADS), 256>>>(table, rel);
    mask16f_kernel<<<dim3(8, NW), 256>>>(mask);
    qkv_gemm_kernel<<<dim3(2, ROWS / 128), 256, GEMM_SMEM>>>(x, qkv_w, qkv_b);
    attn_f16_kernel<<<dim3(HEADS, BATCH), 256, 49152>>>();
    proj_gemm_kernel<<<dim3(2, ROWS / 128), 256, GEMM_SMEM>>>(proj_w, proj_b, out);
}

// round 17
// speedup vs baseline: 1.1220x; 1.0573x over previous
#include <cuda_runtime.h>
#include <cuda_fp16.h>

// Problem constants
#define BATCH   256          // B_
#define NTOK    256          // N tokens per window
#define DIM     192
#define HEADS   6
#define HD      32           // head dim
#define NW      64           // number of windows (mask slices)
#define ROWS    (BATCH*NTOK) // 65536 GEMM rows
#define SCALE   0.17677669529663687f   // 32^-0.5

typedef unsigned int uint;

// ---------------------------------------------------------------------------
// fp16 mma helpers (m16n8k16; gr=lane>>2, tg=lane&3)
// ---------------------------------------------------------------------------
__device__ __forceinline__ uint pkh2(float lo, float hi) {
    __half2 h = __floats2half2_rn(lo, hi);
    return *(uint*)&h;
}
__device__ __forceinline__ float2 h22f2(uint u) {
    return __half22float2(*(__half2*)&u);
}
__device__ __forceinline__ void mma16(float4& c, uint4 a, uint2 b) {
    asm("mma.sync.aligned.m16n8k16.row.col.f32.f16.f16.f32 "
        "{%0,%1,%2,%3},{%4,%5,%6,%7},{%8,%9},{%0,%1,%2,%3};"
        : "+f"(c.x), "+f"(c.y), "+f"(c.z), "+f"(c.w)
        : "r"(a.x), "r"(a.y), "r"(a.z), "r"(a.w), "r"(b.x), "r"(b.y));
}

// ---------------------------------------------------------------------------
// Scratch. q/k/v/att packed f16 pairs. bias/mask pre-permuted into FRAGMENT
// ORDER, warp-contiguous: G[outer][ch(8)][wid(8)][i(4)][lane(32)][q(4)] u32,
// where j = i*4+q = mi*8+r2*4+nt indexes the value at
//   n = wid*32 + mi*16 + r2*8 + (lane>>2),  m2 = ch*16 + nt*4 + (lane&3).
// A warp uint4-load at  base + i*128 + lane*4  is 512B contiguous (4 lines).
// ---------------------------------------------------------------------------
__device__ uint  g_q[BATCH*HEADS*NTOK*16];
__device__ uint  g_k[BATCH*HEADS*NTOK*16];
__device__ uint  g_v[BATCH*HEADS*NTOK*16];
__device__ uint  g_att[ROWS*96];
__device__ uint  g_bias16f[HEADS*8*8*512];   // 786KB
__device__ uint  g_mask16f[NW*8*8*512];      // 8MB

// ---------------------------------------------------------------------------
// Prep: bias gather -> frag order (grid (8 nb, 6 h))
// ---------------------------------------------------------------------------
__global__ void bias16f_kernel(const float* __restrict__ table,
                               const int* __restrict__ rel) {
    __shared__ uint tile[32 * 130];
    int nb = blockIdx.x, h = blockIdx.y, t = threadIdx.x;
#pragma unroll
    for (int i = 0; i < 16; i++) {
        int fid = t + i * 256;          // 4096 = 32 rows x 128 m2
        int r = fid >> 7, m2 = fid & 127;
        int n = nb * 32 + r;
        int r0 = rel[n * 256 + 2 * m2];
        int r1 = rel[n * 256 + 2 * m2 + 1];
        tile[r * 130 + m2] = pkh2(table[r0 * HEADS + h], table[r1 * HEADS + h]);
    }
    __syncthreads();
    for (int ch = 0; ch < 8; ch++) {
#pragma unroll
        for (int k = 0; k < 2; k++) {
            int o = t * 2 + k;          // 512 words per (h,ch,nb)
            int i2 = o >> 7, lane = (o >> 2) & 31, q = o & 3;
            int j  = i2 * 4 + q;
            int mi = j >> 3, r2 = (j >> 2) & 1, nt = j & 3;
            int rl = mi * 16 + r2 * 8 + (lane >> 2);
            int m2 = ch * 16 + nt * 4 + (lane & 3);
            g_bias16f[((((size_t)h * 8 + ch) * 8 + nb) << 9) + o] =
                tile[rl * 130 + m2];
        }
    }
}

// Prep: mask convert -> frag order (grid (8 nb, 64 w))
__global__ void mask16f_kernel(const float* __restrict__ mask) {
    __shared__ uint tile[32 * 130];
    int nb = blockIdx.x, w = blockIdx.y, t = threadIdx.x;
#pragma unroll
    for (int i = 0; i < 8; i++) {
        int fid = t + i * 256;          // 2048 float4 = 32 rows x 64
        int r = fid >> 6, f4 = fid & 63;
        float4 v = *(const float4*)&mask[((size_t)(w * 256 + nb * 32 + r)) * 256 + f4 * 4];
        tile[r * 130 + f4 * 2]     = pkh2(v.x, v.y);
        tile[r * 130 + f4 * 2 + 1] = pkh2(v.z, v.w);
    }
    __syncthreads();
    for (int ch = 0; ch < 8; ch++) {
#pragma unroll
        for (int k = 0; k < 2; k++) {
            int o = t * 2 + k;
            int i2 = o >> 7, lane = (o >> 2) & 31, q = o & 3;
            int j  = i2 * 4 + q;
            int mi = j >> 3, r2 = (j >> 2) & 1, nt = j & 3;
            int rl = mi * 16 + r2 * 8 + (lane >> 2);
            int m2 = ch * 16 + nt * 4 + (lane & 3);
            g_mask16f[((((size_t)w * 8 + ch) * 8 + nb) << 9) + o] =
                tile[rl * 130 + m2];
        }
    }
}

// ---------------------------------------------------------------------------
// fp16 GEMM (unchanged, best R13 config): CTA 128x96xK192, grid (2,512),
// 2 CTAs/SM; chunk-major smem, 8 warps 4(M)x2(N).
// ---------------------------------------------------------------------------
#define AS_WORDS (6 * 128 * 16)   // 12288
#define BS_WORDS (6 * 96 * 16)    //  9216
#define GEMM_SMEM ((AS_WORDS + BS_WORDS) * 4)   // 86016 B

__device__ __forceinline__ uint4 ldA16(const uint* As, int mtb, int kb2,
                                       int kc, int gr, int tg) {
    int r0 = mtb + gr;
    int s  = (r0 & 7) << 1;
    const uint* base = As + (kb2 * 128 + r0) * 16;
    int c0 = (kc * 8 + tg) ^ s;
    int c1 = (kc * 8 + tg + 4) ^ s;
    uint4 a;
    a.x = base[c0];
    a.y = base[128 + c0];
    a.z = base[c1];
    a.w = base[128 + c1];
    return a;
}
__device__ __forceinline__ uint2 ldB16(const uint* Bs, int ntb, int kb2,
                                       int kc, int gr, int tg) {
    int n0 = ntb + gr;
    int s  = (n0 & 7) << 1;
    const uint* base = Bs + (kb2 * 96 + n0) * 16;
    uint2 b;
    b.x = base[(kc * 8 + tg) ^ s];
    b.y = base[(kc * 8 + tg + 4) ^ s];
    return b;
}
__device__ __forceinline__ void stageB96(uint* Bs, const float* __restrict__ W,
                                         int ldw, int cbW, int lane, int wid) {
#pragma unroll
    for (int j = 0; j < 36; j++) {
        int n  = (j % 3) * 32 + lane;
        int kg = wid + 8 * (j / 3);
        float w0 = W[(size_t)(2 * kg) * ldw + cbW + n];
        float w1 = W[(size_t)(2 * kg + 1) * ldw + cbW + n];
        int kb2 = kg >> 4;
        int col = (kg & 15) ^ ((n & 7) << 1);
        Bs[(kb2 * 96 + n) * 16 + col] = pkh2(w0, w1);
    }
}

#define GEMM_COMPUTE96()                                                       \
    _Pragma("unroll")                                                          \
    for (int kb2 = 0; kb2 < 6; kb2++) {                                        \
        _Pragma("unroll")                                                      \
        for (int kc = 0; kc < 2; kc++) {                                       \
            uint4 a[2];                                                        \
            a[0] = ldA16(As, wm * 32, kb2, kc, gr, tg);                        \
            a[1] = ldA16(As, wm * 32 + 16, kb2, kc, gr, tg);                   \
            _Pragma("unroll")                                                  \
            for (int nt = 0; nt < 6; nt++) {                                   \
                uint2 b = ldB16(Bs, wn * 48 + nt * 8, kb2, kc, gr, tg);        \
                mma16(acc[0][nt], a[0], b);                                    \
                mma16(acc[1][nt], a[1], b);                                    \
            }                                                                  \
        }                                                                      \
    }

__global__ __launch_bounds__(256, 2) void qkv_gemm_kernel(
    const float* __restrict__ X, const float* __restrict__ W,
    const float* __restrict__ bias) {
    extern __shared__ uint smg[];
    uint* As = smg;
    uint* Bs = smg + AS_WORDS;
    __shared__ float sBias[576];

    int t    = threadIdx.x;
    int lane = t & 31;
    int wid  = t >> 5;
    int wm   = wid >> 1;
    int wn   = wid & 1;
    int gr   = lane >> 2, tg = lane & 3;
    int nb   = blockIdx.x;
    int rb   = blockIdx.y * 128;

    for (int i = t; i < 576; i += 256) sBias[i] = bias[i];

#pragma unroll
    for (int ii = 0; ii < 24; ii++) {
        int fid = t + ii * 256;
        int row = fid / 48;
        int c4  = (fid - row * 48) * 4;
        float4 v = *(const float4*)&X[(size_t)(rb + row) * DIM + c4];
        int c2  = c4 >> 1;
        int kb2 = c2 >> 4;
        int col = (c2 & 15) ^ ((row & 7) << 1);
        uint2 u;
        u.x = pkh2(v.x, v.y);
        u.y = pkh2(v.z, v.w);
        *(uint2*)&As[(kb2 * 128 + row) * 16 + col] = u;
    }

    for (int mat = 0; mat < 3; mat++) {
        __syncthreads();
        stageB96(Bs, W, 576, mat * 192 + nb * 96, lane, wid);
        __syncthreads();

        float4 acc[2][6];
#pragma unroll
        for (int i = 0; i < 2; i++)
#pragma unroll
            for (int j = 0; j < 6; j++) acc[i][j] = make_float4(0.f, 0.f, 0.f, 0.f);

        GEMM_COMPUTE96()

        uint* dst = (mat == 0) ? g_q : (mat == 1) ? g_k : g_v;
        float sc = (mat == 0) ? SCALE : 1.f;
#pragma unroll
        for (int mt = 0; mt < 2; mt++) {
#pragma unroll
            for (int nt = 0; nt < 6; nt++) {
                float4 c = acc[mt][nt];
                int cl = nb * 96 + wn * 48 + nt * 8 + 2 * tg;
                float b0 = sBias[mat * 192 + cl], b1 = sBias[mat * 192 + cl + 1];
                int h = cl >> 5, d2 = (cl & 31) >> 1;
                int r0 = rb + wm * 32 + mt * 16 + gr;
                uint u0 = pkh2((c.x + b0) * sc, (c.y + b1) * sc);
                uint u1 = pkh2((c.z + b0) * sc, (c.w + b1) * sc);
                dst[(((r0 >> 8) * HEADS + h) * 256 + (r0 & 255)) * 16 + d2] = u0;
                int r1 = r0 + 8;
                dst[(((r1 >> 8) * HEADS + h) * 256 + (r1 & 255)) * 16 + d2] = u1;
            }
        }
    }
}

__global__ __launch_bounds__(256, 2) void proj_gemm_kernel(
    const float* __restrict__ W, const float* __restrict__ bias,
    float* __restrict__ out) {
    extern __shared__ uint smg[];
    uint* As = smg;
    uint* Bs = smg + AS_WORDS;
    __shared__ float sBias[192];

    int t    = threadIdx.x;
    int lane = t & 31;
    int wid  = t >> 5;
    int wm   = wid >> 1;
    int wn   = wid & 1;
    int gr   = lane >> 2, tg = lane & 3;
    int nb   = blockIdx.x;
    int rb   = blockIdx.y * 128;

    if (t < 192) sBias[t] = bias[t];

#pragma unroll
    for (int ii = 0; ii < 24; ii++) {
        int fid = t + ii * 256;
        int row = fid / 48;
        int c2  = (fid - row * 48) * 2;
        uint2 v = *(const uint2*)&g_att[(size_t)(rb + row) * 96 + c2];
        int kb2 = c2 >> 4;
        int col = (c2 & 15) ^ ((row & 7) << 1);
        *(uint2*)&As[(kb2 * 128 + row) * 16 + col] = v;
    }
    stageB96(Bs, W, DIM, nb * 96, lane, wid);
    __syncthreads();

    float4 acc[2][6];
#pragma unroll
    for (int i = 0; i < 2; i++)
#pragma unroll
        for (int j = 0; j < 6; j++) acc[i][j] = make_float4(0.f, 0.f, 0.f, 0.f);

    GEMM_COMPUTE96()

#pragma unroll
    for (int mt = 0; mt < 2; mt++) {
#pragma unroll
        for (int nt = 0; nt < 6; nt++) {
            float4 c = acc[mt][nt];
            int cl = nb * 96 + wn * 48 + nt * 8 + 2 * tg;
            float b0 = sBias[cl], b1 = sBias[cl + 1];
            int r0 = rb + wm * 32 + mt * 16 + gr;
            *(float2*)&out[(size_t)r0 * DIM + cl] =
                make_float2(c.x + b0, c.y + b1);
            *(float2*)&out[(size_t)(r0 + 8) * DIM + cl] =
                make_float2(c.z + b0, c.w + b1);
        }
    }
}

// ---------------------------------------------------------------------------
// fp16 tensor-core attention. One CTA per (b,h); 8 warps x 32 query rows.
// bm values arrive in frag order via WARP-CONTIGUOUS LDG.128 (512B/load,
// 4 lines) — no smem staging. smem = Q/K/V tiles only (48KB).
// ---------------------------------------------------------------------------
__global__ __launch_bounds__(256, 2) void attn_f16_kernel() {
    extern __shared__ uint sm[];
    uint* Ks  = sm;                 // 4096 u32
    uint* Vs  = sm + 4096;          // 4096 u32
    uint* Qs  = sm + 8192;          // 4096 u32

    int h = blockIdx.x;
    int b = blockIdx.y;
    int w = b & (NW - 1);
    int t = threadIdx.x;
    int lane = t & 31;
    int wid = t >> 5;
    int gr = lane >> 2, tg = lane & 3;

    const uint* kg = g_k + (size_t)(b * HEADS + h) * (256 * 16);
    const uint* qg = g_q + (size_t)(b * HEADS + h) * (256 * 16);
    const uint* vg = g_v + (size_t)(b * HEADS + h) * (256 * 16);

#pragma unroll
    for (int i = 0; i < 8; i++) {
        int fid = t + i * 256;
        int key = fid >> 3;
        int p   = (fid & 7) * 2;
        int col = p ^ ((key & 7) << 1);
        *(uint2*)&Ks[key * 16 + col] = *(const uint2*)&kg[key * 16 + p];
        *(uint2*)&Qs[key * 16 + col] = *(const uint2*)&qg[key * 16 + p];
    }
#pragma unroll
    for (int i = 0; i < 4; i++) {
        int fid = t + i * 256;
        int k2  = fid >> 3;
        int dg  = (fid & 7) * 4;
        uint2 r0 = *(const uint2*)&vg[(2 * k2) * 16 + (dg >> 1)];
        uint2 r1 = *(const uint2*)&vg[(2 * k2 + 1) * 16 + (dg >> 1)];
        uint4 o;
        o.x = __byte_perm(r0.x, r1.x, 0x5410);
        o.y = __byte_perm(r0.x, r1.x, 0x7632);
        o.z = __byte_perm(r0.y, r1.y, 0x5410);
        o.w = __byte_perm(r0.y, r1.y, 0x7632);
        *(uint4*)&Vs[k2 * 32 + (dg ^ ((k2 & 3) << 3))] = o;
    }
    __syncthreads();

    int qb = wid * 32;
    uint4 qa[2][2];
#pragma unroll
    for (int mi = 0; mi < 2; mi++) {
#pragma unroll
        for (int kc = 0; kc < 2; kc++) {
            int r0 = qb + mi * 16 + gr;
            int s  = (r0 & 7) << 1;
            qa[mi][kc].x = Qs[r0 * 16 + ((kc * 8 + tg) ^ s)];
            qa[mi][kc].y = Qs[(r0 + 8) * 16 + ((kc * 8 + tg) ^ s)];
            qa[mi][kc].z = Qs[r0 * 16 + ((kc * 8 + tg + 4) ^ s)];
            qa[mi][kc].w = Qs[(r0 + 8) * 16 + ((kc * 8 + tg + 4) ^ s)];
        }
    }

    float4 O[2][4];
#pragma unroll
    for (int mi = 0; mi < 2; mi++)
#pragma unroll
        for (int nt = 0; nt < 4; nt++) O[mi][nt] = make_float4(0.f, 0.f, 0.f, 0.f);
    float lsum[2][2] = {{0.f, 0.f}, {0.f, 0.f}};

    // frag-ordered, warp-contiguous table base pointers
    const uint* Bp = g_bias16f + ((((size_t)h * 8) * 8 + wid) << 9) + lane * 4;
    const uint* Mp = g_mask16f + ((((size_t)w * 8) * 8 + wid) << 9) + lane * 4;

    for (int ch = 0; ch < 8; ch++) {
        // ---- warp-contiguous frag-order bm loads (4 lines each) ----
        uint bf[16], mf[16];
        {
            const uint* bq = Bp + (size_t)ch * 4096;
            const uint* mq = Mp + (size_t)ch * 4096;
#pragma unroll
            for (int i = 0; i < 4; i++) {
                *(uint4*)&bf[i * 4] = *(const uint4*)(bq + i * 128);
                *(uint4*)&mf[i * 4] = *(const uint4*)(mq + i * 128);
            }
        }

        // ---- S = Q * K^T (32 keys) ----
        float4 S[2][4];
#pragma unroll
        for (int mi = 0; mi < 2; mi++)
#pragma unroll
            for (int nt = 0; nt < 4; nt++) S[mi][nt] = make_float4(0.f, 0.f, 0.f, 0.f);
#pragma unroll
        for (int kc = 0; kc < 2; kc++) {
#pragma unroll
            for (int nt = 0; nt < 4; nt++) {
                int key = ch * 32 + nt * 8 + gr;
                int s2  = (key & 7) << 1;
                uint2 bk;
                bk.x = Ks[key * 16 + ((kc * 8 + tg) ^ s2)];
                bk.y = Ks[key * 16 + ((kc * 8 + tg + 4) ^ s2)];
                mma16(S[0][nt], qa[0][kc], bk);
                mma16(S[1][nt], qa[1][kc], bk);
            }
        }

        // ---- softmax numerators; pack P straight into fp16 A-frags ----
        uint4 pa[2][2];
#pragma unroll
        for (int mi = 0; mi < 2; mi++) {
#pragma unroll
            for (int nt = 0; nt < 4; nt++) {
                float2 b0 = h22f2(bf[(mi * 2 + 0) * 4 + nt]);
                float2 m0 = h22f2(mf[(mi * 2 + 0) * 4 + nt]);
                float2 b1 = h22f2(bf[(mi * 2 + 1) * 4 + nt]);
                float2 m1 = h22f2(mf[(mi * 2 + 1) * 4 + nt]);
                float4 s = S[mi][nt];
                float p00 = __expf(s.x + b0.x + m0.x);
                float p01 = __expf(s.y + b0.y + m0.y);
                float p10 = __expf(s.z + b1.x + m1.x);
                float p11 = __expf(s.w + b1.y + m1.y);
                lsum[mi][0] += p00 + p01;
                lsum[mi][1] += p10 + p11;
                uint lo = pkh2(p00, p01);
                uint hi = pkh2(p10, p11);
                int jj = nt >> 1;
                if ((nt & 1) == 0) { pa[mi][jj].x = lo; pa[mi][jj].y = hi; }
                else               { pa[mi][jj].z = lo; pa[mi][jj].w = hi; }
            }
        }

        // ---- O += P * V ----
#pragma unroll
        for (int jj = 0; jj < 2; jj++) {
            int k2b = ch * 16 + jj * 8;
            int rA = k2b + tg, rB = k2b + tg + 4;
#pragma unroll
            for (int nt = 0; nt < 4; nt++) {
                int d0 = nt * 8 + gr;
                uint2 vb;
                vb.x = Vs[rA * 32 + (d0 ^ ((rA & 3) << 3))];
                vb.y = Vs[rB * 32 + (d0 ^ ((rB & 3) << 3))];
                mma16(O[0][nt], pa[0][jj], vb);
                mma16(O[1][nt], pa[1][jj], vb);
            }
        }
    }

    float inv[2][2];
#pragma unroll
    for (int mi = 0; mi < 2; mi++)
#pragma unroll
        for (int r2 = 0; r2 < 2; r2++) {
            float lv = lsum[mi][r2];
            lv += __shfl_xor_sync(0xffffffff, lv, 1);
            lv += __shfl_xor_sync(0xffffffff, lv, 2);
            inv[mi][r2] = 1.f / lv;
        }
#pragma unroll
    for (int mi = 0; mi < 2; mi++) {
#pragma unroll
        for (int nt = 0; nt < 4; nt++) {
            float4 o = O[mi][nt];
            int r0 = b * 256 + qb + mi * 16 + gr;
            int col = h * 16 + nt * 4 + tg;
            g_att[(size_t)r0 * 96 + col] =
                pkh2(o.x * inv[mi][0], o.y * inv[mi][0]);
            g_att[(size_t)(r0 + 8) * 96 + col] =
                pkh2(o.z * inv[mi][1], o.w * inv[mi][1]);
        }
    }
}

// ---------------------------------------------------------------------------
// Launch
// ---------------------------------------------------------------------------
extern "C" void kernel_launch(void* const* d_in, const int* in_sizes, int n_in,
                              void* d_out, int out_size) {
    const float* x        = (const float*)d_in[0];
    const float* mask     = (const float*)d_in[1];
    const float* qkv_w    = (const float*)d_in[2];
    const float* qkv_b    = (const float*)d_in[3];
    const float* proj_w   = (const float*)d_in[4];
    const float* proj_b   = (const float*)d_in[5];
    const float* table    = (const float*)d_in[6];
    const int*   rel      = (const int*)d_in[7];
    float* out = (float*)d_out;

    cudaFuncSetAttribute(attn_f16_kernel,
                         cudaFuncAttributeMaxDynamicSharedMemorySize, 49152);
    cudaFuncSetAttribute(qkv_gemm_kernel,
                         cudaFuncAttributeMaxDynamicSharedMemorySize, GEMM_SMEM);
    cudaFuncSetAttribute(proj_gemm_kernel,
                         cudaFuncAttributeMaxDynamicSharedMemorySize, GEMM_SMEM);

    bias16f_kernel<<<dim3(8, HEADS), 256>>>(table, rel);
    mask16f_kernel<<<dim3(8, NW), 256>>>(mask);
    qkv_gemm_kernel<<<dim3(2, ROWS / 128), 256, GEMM_SMEM>>>(x, qkv_w, qkv_b);
    attn_f16_kernel<<<dim3(HEADS, BATCH), 256, 49152>>>();
    proj_gemm_kernel<<<dim3(2, ROWS / 128), 256, GEMM_SMEM>>>(proj_w, proj_b, out);
}